// round 1
// baseline (speedup 1.0000x reference)
#include <cuda_runtime.h>
#include <cstdint>

#define Bsz 512
#define Hd  256
#define Zd  64
#define Td  64
#define Pd  10000
#define G3  768

// ---------------- scratch (device globals; no allocation allowed) ----------
__device__ float g_h0[Bsz * Hd];
__device__ float g_hping[2][Bsz * Hd];
__device__ float g_gx0[G3];
__device__ float g_WT0[Hd * G3];                 // [k][g] k-major transpose of W_hh0
__device__ float g_WT1[Hd * G3];
__device__ float g_out0[Bsz * Td * Hd];
__device__ float g_out1[Bsz * Td * Hd];
__device__ float g_act[Bsz * Td * Hd];
__device__ float g_gx1[(size_t)Bsz * Td * G3];   // 100.7 MB

// ---------------- helpers ---------------------------------------------------
__device__ __forceinline__ float to_tf32(float x) {
    float y;
    asm("cvt.rna.tf32.f32 %0, %1;" : "=f"(y) : "f"(x));
    return y;
}

__device__ __forceinline__ void mma8(float* d, const uint32_t* a, const uint32_t* b) {
    asm volatile(
        "mma.sync.aligned.m16n8k8.row.col.f32.tf32.tf32.f32 "
        "{%0,%1,%2,%3}, {%4,%5,%6,%7}, {%8,%9}, {%0,%1,%2,%3};\n"
        : "+f"(d[0]), "+f"(d[1]), "+f"(d[2]), "+f"(d[3])
        : "r"(a[0]), "r"(a[1]), "r"(a[2]), "r"(a[3]), "r"(b[0]), "r"(b[1]));
}

__device__ __forceinline__ float elu_f(float x) {
    return x > 0.f ? x : expm1f(x);
}

// ---------------- small prep kernels ---------------------------------------
__global__ void transpose_k(const float* __restrict__ src, int which) {
    int idx = blockIdx.x * 256 + threadIdx.x;   // 768*256 total
    int gI = idx >> 8, k = idx & 255;
    float* dst = which ? g_WT1 : g_WT0;
    dst[k * G3 + gI] = src[idx];
}

__global__ void init_h0_k(const float* __restrict__ z,
                          const float* __restrict__ Wi,
                          const float* __restrict__ bi) {
    int b = blockIdx.x, h = threadIdx.x;
    __shared__ float sz[Zd];
    if (h < Zd) sz[h] = z[b * Zd + h];
    __syncthreads();
    float acc = bi[h];
#pragma unroll
    for (int k = 0; k < Zd; k++) acc += sz[k] * Wi[h * Zd + k];
    g_h0[b * Hd + h] = elu_f(acc);
}

__global__ void gx0_k(const float* __restrict__ emb,
                      const float* __restrict__ Wih,
                      const float* __restrict__ bih) {
    __shared__ float se[Hd];
    se[threadIdx.x] = emb[threadIdx.x];
    __syncthreads();
    int gI = blockIdx.x * 256 + threadIdx.x;     // grid 3 -> 0..767 exact
    float acc = bih[gI];
#pragma unroll 8
    for (int i = 0; i < Hd; i++) acc += se[i] * Wih[gI * Hd + i];
    g_gx0[gI] = acc;
}

// ---------------- GRU step: fused gh-GEMM + gates ---------------------------
// grid (32 b-tiles of 16 rows, 8 h-tiles of 32 cols), 256 threads.
// Each thread: lane = h column, warp owns 2 batch rows; 3 gate dots of K=256.
__global__ void __launch_bounds__(256) gru_step_k(int t, int layer,
                                                  const float* __restrict__ bhh) {
    __shared__ float s_h[16 * 32];
    __shared__ float s_w[32 * 96];
    const float* WT    = layer ? g_WT1 : g_WT0;
    const float* hprev = (t == 0) ? g_h0 : g_hping[t & 1];
    float*       hnext = g_hping[(t + 1) & 1];
    float*       out   = layer ? g_out1 : g_out0;

    const int b0 = blockIdx.x * 16;
    const int hb = blockIdx.y * 32;
    const int tid = threadIdx.x;
    const int w = tid >> 5, lane = tid & 31;

    float ar0 = 0.f, az0 = 0.f, an0 = 0.f;
    float ar1 = 0.f, az1 = 0.f, an1 = 0.f;

    for (int k0 = 0; k0 < Hd; k0 += 32) {
        for (int e = tid; e < 512; e += 256)
            s_h[e] = hprev[(b0 + (e >> 5)) * Hd + k0 + (e & 31)];
        for (int e = tid; e < 3072; e += 256) {
            int kk = e / 96, j = e - kk * 96;
            int seg = j >> 5, jj = j & 31;
            s_w[e] = WT[(k0 + kk) * G3 + seg * Hd + hb + jj];
        }
        __syncthreads();
#pragma unroll 8
        for (int kk = 0; kk < 32; kk++) {
            float w0 = s_w[kk * 96 + lane];
            float w1 = s_w[kk * 96 + 32 + lane];
            float w2 = s_w[kk * 96 + 64 + lane];
            float h0v = s_h[(w * 2) * 32 + kk];       // broadcast
            float h1v = s_h[(w * 2 + 1) * 32 + kk];   // broadcast
            ar0 += h0v * w0; az0 += h0v * w1; an0 += h0v * w2;
            ar1 += h1v * w0; az1 += h1v * w1; an1 += h1v * w2;
        }
        __syncthreads();
    }

    const int hg = hb + lane;
    const float br = bhh[hg], bz = bhh[Hd + hg], bn = bhh[2 * Hd + hg];
#pragma unroll
    for (int r = 0; r < 2; r++) {
        int b = b0 + w * 2 + r;
        float hr = (r ? ar1 : ar0) + br;
        float hz = (r ? az1 : az0) + bz;
        float hn = (r ? an1 : an0) + bn;
        float xr, xz, xn;
        if (layer == 0) {
            xr = g_gx0[hg]; xz = g_gx0[Hd + hg]; xn = g_gx0[2 * Hd + hg];
        } else {
            size_t base = ((size_t)b * Td + t) * G3;
            xr = g_gx1[base + hg]; xz = g_gx1[base + Hd + hg]; xn = g_gx1[base + 2 * Hd + hg];
        }
        float rg = 1.f / (1.f + expf(-(xr + hr)));
        float ug = 1.f / (1.f + expf(-(xz + hz)));
        float ng = tanhf(xn + rg * hn);
        float hp = hprev[b * Hd + hg];
        float hv = (1.f - ug) * ng + ug * hp;
        hnext[b * Hd + hg] = hv;
        out[(b * Td + t) * Hd + hg] = hv;
    }
}

// ---------------- LayerNorm + ELU -------------------------------------------
__global__ void ln_k(const float* __restrict__ lg, const float* __restrict__ lb) {
    const int row = blockIdx.x;
    const int tid = threadIdx.x;
    float v = g_out1[row * Hd + tid];
    __shared__ float red[8], red2[8];
    float s = v;
#pragma unroll
    for (int o = 16; o; o >>= 1) s += __shfl_xor_sync(0xffffffffu, s, o);
    if ((tid & 31) == 0) red[tid >> 5] = s;
    __syncthreads();
    float tot = 0.f;
#pragma unroll
    for (int i = 0; i < 8; i++) tot += red[i];
    float mu = tot * (1.f / 256.f);
    float d = v - mu;
    float q = d * d;
#pragma unroll
    for (int o = 16; o; o >>= 1) q += __shfl_xor_sync(0xffffffffu, q, o);
    if ((tid & 31) == 0) red2[tid >> 5] = q;
    __syncthreads();
    float tq = 0.f;
#pragma unroll
    for (int i = 0; i < 8; i++) tq += red2[i];
    float var = tq * (1.f / 256.f);
    float nrm = d * rsqrtf(var + 1e-5f) * lg[tid] + lb[tid];
    g_act[row * Hd + tid] = elu_f(nrm);
}

// ---------------- tf32 GEMM: C[M,N] = A[M,256] * B[N,256]^T + bias ----------
// 128x128 block tile, 8 warps (4m x 2n), warp tile 32x64, m16n8k8 tf32 mma.
__global__ void __launch_bounds__(256) gemm_k(int a_sel, const float* __restrict__ Bm,
                                              const float* __restrict__ bias,
                                              float* Cext, int c_sel, int N) {
    __shared__ float sA[128][36];
    __shared__ float sB[128][36];
    const float* A = a_sel ? g_act : g_out0;
    float* C = c_sel ? Cext : g_gx1;
    const int m0 = blockIdx.x * 128, n0 = blockIdx.y * 128;
    const int tid = threadIdx.x;
    const int warp = tid >> 5, lane = tid & 31;
    const int wm = warp & 3, wn = warp >> 2;
    const int g = lane >> 2, tg = lane & 3;

    float acc[2][8][4];
#pragma unroll
    for (int i = 0; i < 2; i++)
#pragma unroll
        for (int j = 0; j < 8; j++)
#pragma unroll
            for (int q = 0; q < 4; q++) acc[i][j][q] = 0.f;

    for (int k0 = 0; k0 < 256; k0 += 32) {
#pragma unroll
        for (int i = 0; i < 4; i++) {
            int idx = tid + i * 256;
            int row = idx >> 3, c4 = (idx & 7) << 2;
            float4 v = *(const float4*)(A + (size_t)(m0 + row) * 256 + k0 + c4);
            v.x = to_tf32(v.x); v.y = to_tf32(v.y); v.z = to_tf32(v.z); v.w = to_tf32(v.w);
            *(float4*)&sA[row][c4] = v;
        }
#pragma unroll
        for (int i = 0; i < 4; i++) {
            int idx = tid + i * 256;
            int row = idx >> 3, c4 = (idx & 7) << 2;
            int n = n0 + row;
            float4 v = make_float4(0.f, 0.f, 0.f, 0.f);
            if (n < N) v = *(const float4*)(Bm + (size_t)n * 256 + k0 + c4);
            v.x = to_tf32(v.x); v.y = to_tf32(v.y); v.z = to_tf32(v.z); v.w = to_tf32(v.w);
            *(float4*)&sB[row][c4] = v;
        }
        __syncthreads();
#pragma unroll
        for (int kk = 0; kk < 32; kk += 8) {
            uint32_t af[2][4], bf[8][2];
#pragma unroll
            for (int mi = 0; mi < 2; mi++) {
                int rb = wm * 32 + mi * 16;
                af[mi][0] = __float_as_uint(sA[rb + g][kk + tg]);
                af[mi][1] = __float_as_uint(sA[rb + g + 8][kk + tg]);
                af[mi][2] = __float_as_uint(sA[rb + g][kk + tg + 4]);
                af[mi][3] = __float_as_uint(sA[rb + g + 8][kk + tg + 4]);
            }
#pragma unroll
            for (int ni = 0; ni < 8; ni++) {
                int nb = wn * 64 + ni * 8;
                bf[ni][0] = __float_as_uint(sB[nb + g][kk + tg]);
                bf[ni][1] = __float_as_uint(sB[nb + g][kk + tg + 4]);
            }
#pragma unroll
            for (int mi = 0; mi < 2; mi++)
#pragma unroll
                for (int ni = 0; ni < 8; ni++)
                    mma8(acc[mi][ni], af[mi], bf[ni]);
        }
        __syncthreads();
    }

#pragma unroll
    for (int mi = 0; mi < 2; mi++) {
#pragma unroll
        for (int ni = 0; ni < 8; ni++) {
            int m = m0 + wm * 32 + mi * 16 + g;
            int n = n0 + wn * 64 + ni * 8 + tg * 2;
            if (n < N) {
                float bv = bias[n];
                C[(size_t)m * N + n]       = acc[mi][ni][0] + bv;
                C[(size_t)(m + 8) * N + n] = acc[mi][ni][2] + bv;
            }
            if (n + 1 < N) {
                float bv = bias[n + 1];
                C[(size_t)m * N + n + 1]       = acc[mi][ni][1] + bv;
                C[(size_t)(m + 8) * N + n + 1] = acc[mi][ni][3] + bv;
            }
        }
    }
}

// ---------------- launch ----------------------------------------------------
extern "C" void kernel_launch(void* const* d_in, const int* in_sizes, int n_in,
                              void* d_out, int out_size) {
    const float* z      = (const float*)d_in[0];
    const float* W_init = (const float*)d_in[1];
    const float* b_init = (const float*)d_in[2];
    const float* emb    = (const float*)d_in[3];
    const float* W_ih0  = (const float*)d_in[4];
    const float* W_hh0  = (const float*)d_in[5];
    const float* b_ih0  = (const float*)d_in[6];
    const float* b_hh0  = (const float*)d_in[7];
    const float* W_ih1  = (const float*)d_in[8];
    const float* W_hh1  = (const float*)d_in[9];
    const float* b_ih1  = (const float*)d_in[10];
    const float* b_hh1  = (const float*)d_in[11];
    const float* ln_g   = (const float*)d_in[12];
    const float* ln_b   = (const float*)d_in[13];
    const float* W_out  = (const float*)d_in[14];
    const float* b_out  = (const float*)d_in[15];
    float* out = (float*)d_out;
    (void)in_sizes; (void)n_in; (void)out_size;

    transpose_k<<<768, 256>>>(W_hh0, 0);
    transpose_k<<<768, 256>>>(W_hh1, 1);
    init_h0_k<<<Bsz, 256>>>(z, W_init, b_init);
    gx0_k<<<3, 256>>>(emb, W_ih0, b_ih0);

    for (int t = 0; t < Td; t++)
        gru_step_k<<<dim3(32, 8), 256>>>(t, 0, b_hh0);

    // gx1 = out0 @ W_ih1^T + b_ih1  (M=32768, N=768, K=256)
    gemm_k<<<dim3(256, 6), 256>>>(0, W_ih1, b_ih1, nullptr, 0, G3);

    for (int t = 0; t < Td; t++)
        gru_step_k<<<dim3(32, 8), 256>>>(t, 1, b_hh1);

    ln_k<<<Bsz * Td, 256>>>(ln_g, ln_b);

    // logits = act @ W_out^T + b_out  (M=32768, N=10000, K=256)
    gemm_k<<<dim3(256, 79), 256>>>(1, W_out, b_out, out, 1, Pd);
}

// round 3
// speedup vs baseline: 2.0255x; 2.0255x over previous
#include <cuda_runtime.h>
#include <cstdint>

#define Bsz 512
#define Hd  256
#define Zd  64
#define Td  64
#define Pd  10000
#define G3  768
#define NBLK 128   // persistent GRU grid (1 block/SM, all co-resident)

// ---------------- scratch (device globals) ----------------------------------
__device__ float g_h0[Bsz * Hd];
__device__ float g_hp[2][Bsz * Hd];
__device__ float g_gx0[G3];
__device__ float g_out0[Bsz * Td * Hd];            // tf32-rounded (feeds gx1 GEMM)
__device__ float g_out1[Bsz * Td * Hd];
__device__ float g_act[Bsz * Td * Hd];             // tf32-rounded (feeds final GEMM)
__device__ float g_gx1[(size_t)Bsz * Td * G3];
__device__ float g_wt1[G3 * Hd];                   // tf32 W_ih1
__device__ float g_wto[(size_t)Pd * Hd];           // tf32 W_out
__device__ int   g_bar[4];                         // {cnt0, rel0, cnt1, rel1}

// ---------------- helpers ---------------------------------------------------
__device__ __forceinline__ float to_tf32(float x) {
    float y; asm("cvt.rna.tf32.f32 %0, %1;" : "=f"(y) : "f"(x)); return y;
}
__device__ __forceinline__ void mma8(float* d, const uint32_t* a, const uint32_t* b) {
    asm volatile(
        "mma.sync.aligned.m16n8k8.row.col.f32.tf32.tf32.f32 "
        "{%0,%1,%2,%3}, {%4,%5,%6,%7}, {%8,%9}, {%0,%1,%2,%3};\n"
        : "+f"(d[0]), "+f"(d[1]), "+f"(d[2]), "+f"(d[3])
        : "r"(a[0]), "r"(a[1]), "r"(a[2]), "r"(a[3]), "r"(b[0]), "r"(b[1]));
}
__device__ __forceinline__ float elu_f(float x) { return x > 0.f ? x : expm1f(x); }
__device__ __forceinline__ float sigm_f(float x) { return 1.f / (1.f + expf(-x)); }
__device__ __forceinline__ uint32_t s2u(const void* p) {
    return (uint32_t)__cvta_generic_to_shared(p);
}
__device__ __forceinline__ void cpa16(uint32_t d, const void* s, int srcsize) {
    asm volatile("cp.async.cg.shared.global [%0], [%1], 16, %2;\n"
                 :: "r"(d), "l"(s), "r"(srcsize));
}
__device__ __forceinline__ int ld_acq(const int* p) {
    int v; asm volatile("ld.acquire.gpu.global.b32 %0, [%1];" : "=r"(v) : "l"(p) : "memory");
    return v;
}
__device__ __forceinline__ void st_rel(int* p, int v) {
    asm volatile("st.release.gpu.global.b32 [%0], %1;" :: "l"(p), "r"(v) : "memory");
}

// ---------------- tiny prep kernels -----------------------------------------
__global__ void zero_bar_k() { if (threadIdx.x < 4) g_bar[threadIdx.x] = 0; }

__global__ void cvt_k(const float* __restrict__ s, float* __restrict__ d, int n) {
    int i = blockIdx.x * 256 + threadIdx.x;
    if (i < n) d[i] = to_tf32(s[i]);
}

__global__ void init_h0_k(const float* __restrict__ z,
                          const float* __restrict__ Wi,
                          const float* __restrict__ bi) {
    int b = blockIdx.x, h = threadIdx.x;
    __shared__ float sz[Zd];
    if (h < Zd) sz[h] = z[b * Zd + h];
    __syncthreads();
    float acc = bi[h];
#pragma unroll
    for (int k = 0; k < Zd; k++) acc += sz[k] * Wi[h * Zd + k];
    g_h0[b * Hd + h] = elu_f(acc);
}

__global__ void gx0_k(const float* __restrict__ emb,
                      const float* __restrict__ Wih,
                      const float* __restrict__ bih) {
    int w = (blockIdx.x * blockDim.x + threadIdx.x) >> 5;   // 0..767
    int lane = threadIdx.x & 31;
    const float* wr = Wih + w * Hd;
    float acc = 0.f;
#pragma unroll
    for (int i = 0; i < 8; i++) acc += emb[lane + 32 * i] * wr[lane + 32 * i];
#pragma unroll
    for (int o = 16; o; o >>= 1) acc += __shfl_xor_sync(0xffffffffu, acc, o);
    if (lane == 0) g_gx0[w] = acc + bih[w];
}

// ---------------- persistent GRU layer (64 steps, grid barrier) --------------
// grid 128 = 8 b-tiles(64 rows) x 16 h-tiles(16 cols -> 48 gate cols), 128 thr.
// tf32 mma, A (h_prev) hi+lo split for fp32-accurate recurrence.
#define SB_STRIDE 260
#define GRU_SMEM ((48 * SB_STRIDE + 64 * SB_STRIDE) * 4)

__global__ void __launch_bounds__(128) gru_layer_k(int layer,
                                                   const float* __restrict__ Whh,
                                                   const float* __restrict__ bhh) {
    extern __shared__ float sm[];
    float* sB = sm;                     // [48][260] tf32 weights, resident all steps
    float* sA = sm + 48 * SB_STRIDE;    // [64][260] h_prev fp32
    __shared__ float s_bias[48];
    __shared__ float s_gx0[48];

    const int tid = threadIdx.x;
    const int warp = tid >> 5, lane = tid & 31;
    const int g = lane >> 2, tg = lane & 3;
    const int bt = blockIdx.x & 7, ht = blockIdx.x >> 3;
    const int b0 = bt * 64, hb = ht * 16;
    int* cnt = &g_bar[layer * 2];
    int* rel = cnt + 1;

    // load weight tile once: rows j=gate*16+hc  -> W row gate*256 + hb + hc
#pragma unroll
    for (int i = 0; i < 24; i++) {
        int p = tid + i * 128;
        int r = p >> 6, c4 = (p & 63) << 2;
        int gate = r >> 4, hc = r & 15;
        float4 v = *(const float4*)(Whh + ((gate << 8) + hb + hc) * Hd + c4);
        v.x = to_tf32(v.x); v.y = to_tf32(v.y); v.z = to_tf32(v.z); v.w = to_tf32(v.w);
        *(float4*)&sB[r * SB_STRIDE + c4] = v;
    }
    if (tid < 48) {
        int gate = tid >> 4, hc = tid & 15;
        s_bias[tid] = bhh[(gate << 8) + hb + hc];
        if (layer == 0) s_gx0[tid] = g_gx0[(gate << 8) + hb + hc];
    }

    const int rb = warp * 16;

    for (int t = 0; t < Td; t++) {
        const float* hprev = (t == 0) ? g_h0 : g_hp[t & 1];
        float* hnext = g_hp[(t + 1) & 1];

        // load h_prev tile (fp32)
#pragma unroll
        for (int i = 0; i < 32; i++) {
            int p = tid + i * 128;
            int r = p >> 6, c4 = (p & 63) << 2;
            *(float4*)&sA[r * SB_STRIDE + c4] =
                *(const float4*)(hprev + (b0 + r) * Hd + c4);
        }
        __syncthreads();

        float acc[6][4];
#pragma unroll
        for (int ni = 0; ni < 6; ni++)
#pragma unroll
            for (int q = 0; q < 4; q++) acc[ni][q] = 0.f;

#pragma unroll 4
        for (int kk = 0; kk < Hd; kk += 8) {
            float a0 = sA[(rb + g) * SB_STRIDE + kk + tg];
            float a1 = sA[(rb + g + 8) * SB_STRIDE + kk + tg];
            float a2 = sA[(rb + g) * SB_STRIDE + kk + tg + 4];
            float a3 = sA[(rb + g + 8) * SB_STRIDE + kk + tg + 4];
            float h0 = to_tf32(a0), h1 = to_tf32(a1), h2 = to_tf32(a2), h3 = to_tf32(a3);
            uint32_t ah[4] = {__float_as_uint(h0), __float_as_uint(h1),
                              __float_as_uint(h2), __float_as_uint(h3)};
            uint32_t al[4] = {__float_as_uint(to_tf32(a0 - h0)), __float_as_uint(to_tf32(a1 - h1)),
                              __float_as_uint(to_tf32(a2 - h2)), __float_as_uint(to_tf32(a3 - h3))};
            uint32_t bf[6][2];
#pragma unroll
            for (int ni = 0; ni < 6; ni++) {
                bf[ni][0] = __float_as_uint(sB[(ni * 8 + g) * SB_STRIDE + kk + tg]);
                bf[ni][1] = __float_as_uint(sB[(ni * 8 + g) * SB_STRIDE + kk + tg + 4]);
            }
#pragma unroll
            for (int ni = 0; ni < 6; ni++) {
                mma8(acc[ni], ah, bf[ni]);
                mma8(acc[ni], al, bf[ni]);
            }
        }

        // fused gates: thread holds r/z/n for 8 (row, hcol) pairs
#pragma unroll
        for (int j = 0; j < 2; j++) {
#pragma unroll
            for (int comp = 0; comp < 4; comp++) {
                int rl = rb + g + ((comp & 2) ? 8 : 0);
                int b = b0 + rl;
                int hc = j * 8 + 2 * tg + (comp & 1);
                int hg = hb + hc;
                float ghr = acc[j][comp]     + s_bias[hc];
                float ghz = acc[2 + j][comp] + s_bias[16 + hc];
                float ghn = acc[4 + j][comp] + s_bias[32 + hc];
                float xr, xz, xn;
                if (layer == 0) {
                    xr = s_gx0[hc]; xz = s_gx0[16 + hc]; xn = s_gx0[32 + hc];
                } else {
                    size_t base = ((size_t)b * Td + t) * G3;
                    xr = g_gx1[base + hg];
                    xz = g_gx1[base + Hd + hg];
                    xn = g_gx1[base + 2 * Hd + hg];
                }
                float rg = sigm_f(xr + ghr);
                float ug = sigm_f(xz + ghz);
                float ng = tanhf(xn + rg * ghn);
                float hp = sA[rl * SB_STRIDE + hg];
                float hv = (1.f - ug) * ng + ug * hp;
                hnext[b * Hd + hg] = hv;
                size_t ob = ((size_t)b * Td + t) * Hd + hg;
                if (layer == 0) g_out0[ob] = to_tf32(hv);
                else            g_out1[ob] = hv;
            }
        }

        if (t < Td - 1) {                 // device-wide barrier between steps
            __syncthreads();
            if (tid == 0) {
                __threadfence();
                if (atomicAdd(cnt, 1) == NBLK - 1) {
                    atomicExch(cnt, 0);
                    __threadfence();
                    st_rel(rel, t + 1);
                }
                while (ld_acq(rel) < t + 1) __nanosleep(40);
            }
            __syncthreads();
        }
    }
}

// ---------------- LayerNorm + ELU (writes tf32-rounded activations) ----------
__global__ void ln_k(const float* __restrict__ lg, const float* __restrict__ lb) {
    const int row = blockIdx.x;
    const int tid = threadIdx.x;
    float v = g_out1[row * Hd + tid];
    __shared__ float red[8], red2[8];
    float s = v;
#pragma unroll
    for (int o = 16; o; o >>= 1) s += __shfl_xor_sync(0xffffffffu, s, o);
    if ((tid & 31) == 0) red[tid >> 5] = s;
    __syncthreads();
    float tot = 0.f;
#pragma unroll
    for (int i = 0; i < 8; i++) tot += red[i];
    float mu = tot * (1.f / 256.f);
    float d = v - mu;
    float q = d * d;
#pragma unroll
    for (int o = 16; o; o >>= 1) q += __shfl_xor_sync(0xffffffffu, q, o);
    if ((tid & 31) == 0) red2[tid >> 5] = q;
    __syncthreads();
    float tq = 0.f;
#pragma unroll
    for (int i = 0; i < 8; i++) tq += red2[i];
    float var = tq * (1.f / 256.f);
    float nrm = d * rsqrtf(var + 1e-5f) * lg[tid] + lb[tid];
    g_act[row * Hd + tid] = to_tf32(elu_f(nrm));
}

// ---------------- cp.async double-buffered tf32 GEMM -------------------------
// C[M,N] = A[M,256] @ B[N,256]^T + bias.  A,B already tf32-rounded.
// 128x128 tile, 8 warps (4m x 2n), m16n8k8, 2-stage pipeline.
#define GSTG 4608                     // floats per half-stage (128*36)
#define GEMM_SMEM (2 * 2 * GSTG * 4)  // 73728 B

__global__ void __launch_bounds__(256) gemm2_k(const float* __restrict__ A,
                                               const float* __restrict__ Bm,
                                               const float* __restrict__ bias,
                                               float* __restrict__ C, int N) {
    extern __shared__ float sm[];
    const int m0 = blockIdx.x * 128, n0 = blockIdx.y * 128;
    const int tid = threadIdx.x;
    const int warp = tid >> 5, lane = tid & 31;
    const int wm = warp & 3, wn = warp >> 2;
    const int g = lane >> 2, tg = lane & 3;

    float acc[2][8][4];
#pragma unroll
    for (int i = 0; i < 2; i++)
#pragma unroll
        for (int j = 0; j < 8; j++)
#pragma unroll
            for (int q = 0; q < 4; q++) acc[i][j][q] = 0.f;

    auto load_stage = [&](int s, int k0) {
        float* base = sm + s * 2 * GSTG;
#pragma unroll
        for (int i = 0; i < 4; i++) {
            int idx = tid + i * 256;
            int row = idx >> 3, c4 = (idx & 7) << 2;
            cpa16(s2u(base + row * 36 + c4),
                  A + (size_t)(m0 + row) * Hd + k0 + c4, 16);
        }
#pragma unroll
        for (int i = 0; i < 4; i++) {
            int idx = tid + i * 256;
            int row = idx >> 3, c4 = (idx & 7) << 2;
            int n = n0 + row;
            const float* src = Bm + (size_t)(n < N ? n : 0) * Hd + k0 + c4;
            cpa16(s2u(base + GSTG + row * 36 + c4), src, (n < N) ? 16 : 0);
        }
        asm volatile("cp.async.commit_group;\n" ::: "memory");
    };

    load_stage(0, 0);
    for (int kc = 0; kc < 8; kc++) {
        int cur = kc & 1;
        if (kc < 7) {
            load_stage(cur ^ 1, (kc + 1) * 32);
            asm volatile("cp.async.wait_group 1;\n" ::: "memory");
        } else {
            asm volatile("cp.async.wait_group 0;\n" ::: "memory");
        }
        __syncthreads();
        const float* sA = sm + cur * 2 * GSTG;
        const float* sB = sA + GSTG;
#pragma unroll
        for (int kk = 0; kk < 32; kk += 8) {
            uint32_t af[2][4], bf[8][2];
#pragma unroll
            for (int mi = 0; mi < 2; mi++) {
                int r0 = wm * 32 + mi * 16;
                af[mi][0] = __float_as_uint(sA[(r0 + g) * 36 + kk + tg]);
                af[mi][1] = __float_as_uint(sA[(r0 + g + 8) * 36 + kk + tg]);
                af[mi][2] = __float_as_uint(sA[(r0 + g) * 36 + kk + tg + 4]);
                af[mi][3] = __float_as_uint(sA[(r0 + g + 8) * 36 + kk + tg + 4]);
            }
#pragma unroll
            for (int ni = 0; ni < 8; ni++) {
                int nb = wn * 64 + ni * 8;
                bf[ni][0] = __float_as_uint(sB[(nb + g) * 36 + kk + tg]);
                bf[ni][1] = __float_as_uint(sB[(nb + g) * 36 + kk + tg + 4]);
            }
#pragma unroll
            for (int mi = 0; mi < 2; mi++)
#pragma unroll
                for (int ni = 0; ni < 8; ni++)
                    mma8(acc[mi][ni], af[mi], bf[ni]);
        }
        __syncthreads();
    }

#pragma unroll
    for (int mi = 0; mi < 2; mi++) {
#pragma unroll
        for (int ni = 0; ni < 8; ni++) {
            int m = m0 + wm * 32 + mi * 16 + g;
            int n = n0 + wn * 64 + ni * 8 + tg * 2;
            if (n < N) {
                float bv = bias[n];
                C[(size_t)m * N + n]       = acc[mi][ni][0] + bv;
                C[(size_t)(m + 8) * N + n] = acc[mi][ni][2] + bv;
            }
            if (n + 1 < N) {
                float bv = bias[n + 1];
                C[(size_t)m * N + n + 1]       = acc[mi][ni][1] + bv;
                C[(size_t)(m + 8) * N + n + 1] = acc[mi][ni][3] + bv;
            }
        }
    }
}

// ---------------- launch ----------------------------------------------------
extern "C" void kernel_launch(void* const* d_in, const int* in_sizes, int n_in,
                              void* d_out, int out_size) {
    const float* z      = (const float*)d_in[0];
    const float* W_init = (const float*)d_in[1];
    const float* b_init = (const float*)d_in[2];
    const float* emb    = (const float*)d_in[3];
    const float* W_ih0  = (const float*)d_in[4];
    const float* W_hh0  = (const float*)d_in[5];
    const float* b_ih0  = (const float*)d_in[6];
    const float* b_hh0  = (const float*)d_in[7];
    const float* W_ih1  = (const float*)d_in[8];
    const float* W_hh1  = (const float*)d_in[9];
    const float* b_ih1  = (const float*)d_in[10];
    const float* b_hh1  = (const float*)d_in[11];
    const float* ln_g   = (const float*)d_in[12];
    const float* ln_b   = (const float*)d_in[13];
    const float* W_out  = (const float*)d_in[14];
    const float* b_out  = (const float*)d_in[15];
    float* out = (float*)d_out;
    (void)in_sizes; (void)n_in; (void)out_size;

    float *p_out0, *p_act, *p_gx1, *p_wt1, *p_wto;
    cudaGetSymbolAddress((void**)&p_out0, g_out0);
    cudaGetSymbolAddress((void**)&p_act,  g_act);
    cudaGetSymbolAddress((void**)&p_gx1,  g_gx1);
    cudaGetSymbolAddress((void**)&p_wt1,  g_wt1);
    cudaGetSymbolAddress((void**)&p_wto,  g_wto);

    cudaFuncSetAttribute(gru_layer_k, cudaFuncAttributeMaxDynamicSharedMemorySize, GRU_SMEM);
    cudaFuncSetAttribute(gemm2_k,     cudaFuncAttributeMaxDynamicSharedMemorySize, GEMM_SMEM);

    zero_bar_k<<<1, 32>>>();
    cvt_k<<<(G3 * Hd + 255) / 256, 256>>>(W_ih1, p_wt1, G3 * Hd);
    cvt_k<<<(Pd * Hd + 255) / 256, 256>>>(W_out, p_wto, Pd * Hd);
    init_h0_k<<<Bsz, 256>>>(z, W_init, b_init);
    gx0_k<<<96, 256>>>(emb, W_ih0, b_ih0);

    // layer 0 (persistent, 64 steps)
    gru_layer_k<<<NBLK, 128, GRU_SMEM>>>(0, W_hh0, b_hh0);

    // gx1 = out0 @ W_ih1^T + b_ih1   (M=32768, N=768, K=256)
    gemm2_k<<<dim3(256, 6), 256, GEMM_SMEM>>>(p_out0, p_wt1, b_ih1, p_gx1, G3);

    // layer 1 (persistent, 64 steps)
    gru_layer_k<<<NBLK, 128, GRU_SMEM>>>(1, W_hh1, b_hh1);

    ln_k<<<Bsz * Td, 256>>>(ln_g, ln_b);

    // logits = act @ W_out^T + b_out  (M=32768, N=10000, K=256)
    gemm2_k<<<dim3(256, 79), 256, GEMM_SMEM>>>(p_act, p_wto, b_out, out, Pd);
}